// round 4
// baseline (speedup 1.0000x reference)
#include <cuda_runtime.h>
#include <mma.h>
#include <cstdint>

using namespace nvcuda;

// Problem constants
#define Bn    512
#define Hh    50
#define Tt    1024
#define STATE 13
#define CTRL  4
#define LAT   128
#define HID   256
#define Dd    8            // decimation factor
#define Jn    (Tt / Dd)    // 128 sequential steps / j-tiles per batch

// ---------------- scratch (no allocations allowed) ----------------
__device__ float g_h[Bn * HID];                        // 0.5 MB
__device__ float g_E[(size_t)Bn * LAT * LAT];          // 32 MB   delta (A = I + delta)
__device__ float g_E2[(size_t)Bn * LAT * LAT];         // 32 MB   E2 = (I+E)^2 - I
__device__ float g_E4[(size_t)Bn * LAT * LAT];         // 32 MB
__device__ float g_A8[(size_t)Bn * LAT * LAT];         // 32 MB   A^8 (identity included)
__device__ float g_P[(size_t)Bn * Jn * LAT];           // 33.5 MB Horner state -> d_j
__device__ float g_Bm[Bn * LAT * CTRL];                // 1 MB
__device__ float g_z[(size_t)Bn * (Tt + 1) * LAT];     // 268.8 MB z trajectory

// ---------------- f32x2 packed FMA helpers ----------------
__device__ __forceinline__ unsigned long long pack2(float x, float y) {
    unsigned long long r;
    asm("mov.b64 %0, {%1, %2};" : "=l"(r) : "f"(x), "f"(y));
    return r;
}
__device__ __forceinline__ void unpack2(unsigned long long v, float& x, float& y) {
    asm("mov.b64 {%0, %1}, %2;" : "=f"(x), "=f"(y) : "l"(v));
}
__device__ __forceinline__ void ffma2(unsigned long long& d, unsigned long long a,
                                      unsigned long long b) {
    asm("fma.rn.f32x2 %0, %1, %2, %3;" : "=l"(d) : "l"(a), "l"(b), "l"(d));
}
__device__ __forceinline__ float dot4(float4 a, float4 b) {
    return a.x * b.x + a.y * b.y + a.z * b.z + a.w * b.w;
}

// ---------------- kernel 1: context mean + tanh MLP ----------------
__global__ void k_ctxt(const float* __restrict__ xh, const float* __restrict__ uh,
                       const float* __restrict__ Wc, const float* __restrict__ bc) {
    int b = blockIdx.x;
    int tid = threadIdx.x;
    __shared__ float m[STATE + CTRL];

    if (tid < STATE + CTRL) {
        float s = 0.f;
        if (tid < STATE) {
            const float* p = xh + (size_t)b * Hh * STATE + tid;
            for (int r = 0; r < Hh; r++) s += p[r * STATE];
        } else {
            const float* p = uh + (size_t)b * Hh * CTRL + (tid - STATE);
            for (int r = 0; r < Hh; r++) s += p[r * CTRL];
        }
        m[tid] = s * (1.0f / (float)Hh);
    }
    __syncthreads();

    float acc = bc[tid];
#pragma unroll
    for (int c = 0; c < STATE + CTRL; c++) acc += m[c] * Wc[c * HID + tid];
    g_h[b * HID + tid] = tanhf(acc);
}

// ---------------- kernel 2: E = h @ W_A + b_A  (FFMA2 tiled GEMM, NO identity) ----
#define BM 32
#define BN 256
#define BK 16
__global__ void __launch_bounds__(256)
k_gemmE(const float* __restrict__ WA, const float* __restrict__ bA) {
    __shared__ float hs[BK][BM + 4];
    __shared__ float Ws[BK][BN];
    int tid = threadIdx.x;
    int c0 = blockIdx.x * BN;
    int b0 = blockIdx.y * BM;
    int ry = tid >> 5;
    int cx = tid & 31;

    unsigned long long acc[4][4];
#pragma unroll
    for (int i = 0; i < 4; i++)
#pragma unroll
        for (int j = 0; j < 4; j++) acc[i][j] = 0ULL;

    for (int k0 = 0; k0 < HID; k0 += BK) {
        for (int idx = tid; idx < BM * BK; idx += 256) {
            int bb = idx >> 4, kk = idx & 15;
            hs[kk][bb] = g_h[(b0 + bb) * HID + k0 + kk];
        }
        for (int idx = tid; idx < (BK * BN) / 4; idx += 256) {
            int kk = idx >> 6, cc4 = idx & 63;
            *(float4*)&Ws[kk][cc4 * 4] =
                *(const float4*)&WA[(size_t)(k0 + kk) * (LAT * LAT) + c0 + cc4 * 4];
        }
        __syncthreads();
#pragma unroll
        for (int kk = 0; kk < BK; kk++) {
            unsigned long long aa[4];
#pragma unroll
            for (int i = 0; i < 4; i++) {
                float av = hs[kk][ry * 4 + i];
                aa[i] = pack2(av, av);
            }
            ulonglong2 w01 = *(const ulonglong2*)&Ws[kk][cx * 8];
            ulonglong2 w23 = *(const ulonglong2*)&Ws[kk][cx * 8 + 4];
#pragma unroll
            for (int i = 0; i < 4; i++) {
                ffma2(acc[i][0], aa[i], w01.x);
                ffma2(acc[i][1], aa[i], w01.y);
                ffma2(acc[i][2], aa[i], w23.x);
                ffma2(acc[i][3], aa[i], w23.y);
            }
        }
        __syncthreads();
    }
#pragma unroll
    for (int i = 0; i < 4; i++) {
        int b = b0 + ry * 4 + i;
        float v[8];
#pragma unroll
        for (int j = 0; j < 4; j++) unpack2(acc[i][j], v[j * 2], v[j * 2 + 1]);
#pragma unroll
        for (int j = 0; j < 8; j++) v[j] += bA[c0 + cx * 8 + j];
        float* dst = g_E + (size_t)b * (LAT * LAT) + c0 + cx * 8;
        *(float4*)dst = make_float4(v[0], v[1], v[2], v[3]);
        *(float4*)(dst + 4) = make_float4(v[4], v[5], v[6], v[7]);
    }
}

// ---------------- kernel 3: B_mat = h @ W_B + b_B ----------------
__global__ void k_gemmB(const float* __restrict__ WB, const float* __restrict__ bB) {
    int b = blockIdx.x;
    int tid = threadIdx.x;
    __shared__ float hs[HID];
    hs[tid] = g_h[b * HID + tid];
    __syncthreads();
    for (int c = tid; c < LAT * CTRL; c += 256) {
        float acc = bB[c];
#pragma unroll 8
        for (int k = 0; k < HID; k++) acc += hs[k] * WB[k * (LAT * CTRL) + c];
        g_Bm[b * (LAT * CTRL) + c] = acc;
    }
}

// ---------------- kernel: P_0[b][j][i] = c_{8j}[i] = Bm[b] @ u[b][8j] -------------
__global__ void k_cinit(const float* __restrict__ u) {
    int b = blockIdx.x;
    int tid = threadIdx.x;
    const float4* bm = (const float4*)g_Bm + b * LAT;
    for (int idx = tid; idx < Jn * LAT; idx += 256) {
        int j = idx >> 7, i = idx & 127;
        float4 u4 = *(const float4*)&u[((size_t)b * Tt + Dd * j) * CTRL];
        g_P[((size_t)b * Jn + j) * LAT + i] = dot4(bm[i], u4);
    }
}

// =====================================================================
// wmma tf32 helpers: each CTA computes one [128,128,128] batch GEMM.
// Warp layout: 8 warps = (wm 0..3: 32 rows) x (wn 0..1: 64 cols).
// Per warp: C frags fc[2 m-tiles][4 n-tiles] of m16n16k8 f32.
// =====================================================================
#define LDT 40   // smem tile leading dim (floats)

typedef wmma::fragment<wmma::matrix_a, 16, 16, 8, wmma::precision::tf32, wmma::row_major> FragA;
typedef wmma::fragment<wmma::matrix_b, 16, 16, 8, wmma::precision::tf32, wmma::col_major> FragBc;
typedef wmma::fragment<wmma::matrix_b, 16, 16, 8, wmma::precision::tf32, wmma::row_major> FragBr;
typedef wmma::fragment<wmma::accumulator, 16, 16, 8, float> FragC;

__device__ __forceinline__ void cvt_tf32_a(FragA& f) {
#pragma unroll
    for (int e = 0; e < f.num_elements; e++) f.x[e] = wmma::__float_to_tf32(f.x[e]);
}
template <typename FB>
__device__ __forceinline__ void cvt_tf32_b(FB& f) {
#pragma unroll
    for (int e = 0; e < f.num_elements; e++) f.x[e] = wmma::__float_to_tf32(f.x[e]);
}

// ---------------- squaring: out = in@in + 2*in (+I on last) ----------------
__global__ void __launch_bounds__(256, 2)
k_sq(const float* __restrict__ in, float* __restrict__ out, int addI) {
    __shared__ float sA[128 * LDT];        // A rows (also epilogue scratch)
    __shared__ float sB[32 * 136];         // B row-major chunk
    int b = blockIdx.x, tid = threadIdx.x, w = tid >> 5, lane = tid & 31;
    int wm = w & 3, wn = w >> 2;
    const float* Inb = in + (size_t)b * LAT * LAT;
    float* Outb = out + (size_t)b * LAT * LAT;

    FragC fc[2][4];
#pragma unroll
    for (int mt = 0; mt < 2; mt++)
#pragma unroll
        for (int nt = 0; nt < 4; nt++) wmma::fill_fragment(fc[mt][nt], 0.f);

    for (int k0 = 0; k0 < 128; k0 += 32) {
        for (int t = tid; t < 1024; t += 256) {
            int row = t >> 3, c4 = (t & 7) * 4;
            *(float4*)&sA[row * LDT + c4] = *(const float4*)&Inb[row * 128 + k0 + c4];
        }
        for (int t = tid; t < 1024; t += 256) {
            int kk = t >> 5, c4 = (t & 31) * 4;
            *(float4*)&sB[kk * 136 + c4] = *(const float4*)&Inb[(k0 + kk) * 128 + c4];
        }
        __syncthreads();
#pragma unroll
        for (int kk = 0; kk < 4; kk++) {
            FragA fa[2];
#pragma unroll
            for (int mt = 0; mt < 2; mt++) {
                wmma::load_matrix_sync(fa[mt], &sA[(wm * 32 + mt * 16) * LDT + kk * 8], LDT);
                cvt_tf32_a(fa[mt]);
            }
#pragma unroll
            for (int nt = 0; nt < 4; nt++) {
                FragBr fb;
                wmma::load_matrix_sync(fb, &sB[(kk * 8) * 136 + wn * 64 + nt * 16], 136);
                cvt_tf32_b(fb);
                wmma::mma_sync(fc[0][nt], fa[0], fb, fc[0][nt]);
                wmma::mma_sync(fc[1][nt], fa[1], fb, fc[1][nt]);
            }
        }
        __syncthreads();
    }
    // epilogue
    float* strip = sA + w * 640;
#pragma unroll
    for (int ph = 0; ph < 4; ph++) {
        int mt = ph >> 1, np = ph & 1;
        wmma::store_matrix_sync(strip, fc[mt][np * 2], LDT, wmma::mem_row_major);
        wmma::store_matrix_sync(strip + 16, fc[mt][np * 2 + 1], LDT, wmma::mem_row_major);
        __syncwarp();
#pragma unroll
        for (int rep = 0; rep < 4; rep++) {
            int rl = (lane >> 3) + rep * 4;
            int cl = (lane & 7) * 4;
            float4 acc4 = *(float4*)&strip[rl * LDT + cl];
            int grow = wm * 32 + mt * 16 + rl;
            int gcol = wn * 64 + np * 32 + cl;
            float4 iv = *(const float4*)&Inb[grow * 128 + gcol];
            float4 res;
            res.x = acc4.x + 2.f * iv.x + ((addI && grow == gcol + 0) ? 1.f : 0.f);
            res.y = acc4.y + 2.f * iv.y + ((addI && grow == gcol + 1) ? 1.f : 0.f);
            res.z = acc4.z + 2.f * iv.z + ((addI && grow == gcol + 2) ? 1.f : 0.f);
            res.w = acc4.w + 2.f * iv.w + ((addI && grow == gcol + 3) ? 1.f : 0.f);
            *(float4*)&Outb[grow * 128 + gcol] = res;
        }
        __syncwarp();
    }
}

// ---------------- Horner round: P <- P + P@E^T + c_{8j+r}  (in-place) ----------
__global__ void __launch_bounds__(256, 2)
k_hor(const float* __restrict__ u, int r) {
    __shared__ float sA[128 * LDT];
    __shared__ float sB[128 * LDT];
    int b = blockIdx.x, tid = threadIdx.x, w = tid >> 5, lane = tid & 31;
    int wm = w & 3, wn = w >> 2;
    float* Pb = g_P + (size_t)b * Jn * LAT;
    const float* Eb = g_E + (size_t)b * LAT * LAT;
    const float4* bm = (const float4*)g_Bm + b * LAT;

    FragC fc[2][4];
#pragma unroll
    for (int mt = 0; mt < 2; mt++)
#pragma unroll
        for (int nt = 0; nt < 4; nt++) wmma::fill_fragment(fc[mt][nt], 0.f);

    for (int k0 = 0; k0 < 128; k0 += 32) {
        for (int t = tid; t < 1024; t += 256) {
            int row = t >> 3, c4 = (t & 7) * 4;
            *(float4*)&sA[row * LDT + c4] = *(const float4*)&Pb[row * 128 + k0 + c4];
            *(float4*)&sB[row * LDT + c4] = *(const float4*)&Eb[row * 128 + k0 + c4];
        }
        __syncthreads();
#pragma unroll
        for (int kk = 0; kk < 4; kk++) {
            FragA fa[2];
#pragma unroll
            for (int mt = 0; mt < 2; mt++) {
                wmma::load_matrix_sync(fa[mt], &sA[(wm * 32 + mt * 16) * LDT + kk * 8], LDT);
                cvt_tf32_a(fa[mt]);
            }
#pragma unroll
            for (int nt = 0; nt < 4; nt++) {
                FragBc fb;   // col-major view of E => B = E^T
                wmma::load_matrix_sync(fb, &sB[(wn * 64 + nt * 16) * LDT + kk * 8], LDT);
                cvt_tf32_b(fb);
                wmma::mma_sync(fc[0][nt], fa[0], fb, fc[0][nt]);
                wmma::mma_sync(fc[1][nt], fa[1], fb, fc[1][nt]);
            }
        }
        __syncthreads();
    }
    float* strip = sA + w * 640;
#pragma unroll
    for (int ph = 0; ph < 4; ph++) {
        int mt = ph >> 1, np = ph & 1;
        wmma::store_matrix_sync(strip, fc[mt][np * 2], LDT, wmma::mem_row_major);
        wmma::store_matrix_sync(strip + 16, fc[mt][np * 2 + 1], LDT, wmma::mem_row_major);
        __syncwarp();
#pragma unroll
        for (int rep = 0; rep < 4; rep++) {
            int rl = (lane >> 3) + rep * 4;
            int cl = (lane & 7) * 4;
            float4 acc4 = *(float4*)&strip[rl * LDT + cl];
            int grow = wm * 32 + mt * 16 + rl;   // j
            int gcol = wn * 64 + np * 32 + cl;   // i
            int t = Dd * grow + r;
            float4 u4 = *(const float4*)&u[((size_t)b * Tt + t) * CTRL];
            float* outp = &Pb[grow * 128 + gcol];
            float4 pv = *(float4*)outp;
            float4 res;
            res.x = acc4.x + pv.x + dot4(bm[gcol + 0], u4);
            res.y = acc4.y + pv.y + dot4(bm[gcol + 1], u4);
            res.z = acc4.z + pv.z + dot4(bm[gcol + 2], u4);
            res.w = acc4.w + pv.w + dot4(bm[gcol + 3], u4);
            *(float4*)outp = res;
        }
        __syncwarp();
    }
}

// ---------------- recovery round: z_{8j+r} = z_{8j+r-1} + z_prev@E^T + c_{8j+r-1} --
__global__ void __launch_bounds__(256, 2)
k_rec(const float* __restrict__ u, int r) {
    __shared__ float sA[128 * LDT];
    __shared__ float sB[128 * LDT];
    int b = blockIdx.x, tid = threadIdx.x, w = tid >> 5, lane = tid & 31;
    int wm = w & 3, wn = w >> 2;
    const float* Eb = g_E + (size_t)b * LAT * LAT;
    const float4* bm = (const float4*)g_Bm + b * LAT;
    float* Zb = g_z + (size_t)b * (Tt + 1) * LAT;

    FragC fc[2][4];
#pragma unroll
    for (int mt = 0; mt < 2; mt++)
#pragma unroll
        for (int nt = 0; nt < 4; nt++) wmma::fill_fragment(fc[mt][nt], 0.f);

    for (int k0 = 0; k0 < 128; k0 += 32) {
        for (int t = tid; t < 1024; t += 256) {
            int row = t >> 3, c4 = (t & 7) * 4;
            *(float4*)&sA[row * LDT + c4] =
                *(const float4*)&Zb[((size_t)(Dd * row + r - 1)) * LAT + k0 + c4];
            *(float4*)&sB[row * LDT + c4] = *(const float4*)&Eb[row * 128 + k0 + c4];
        }
        __syncthreads();
#pragma unroll
        for (int kk = 0; kk < 4; kk++) {
            FragA fa[2];
#pragma unroll
            for (int mt = 0; mt < 2; mt++) {
                wmma::load_matrix_sync(fa[mt], &sA[(wm * 32 + mt * 16) * LDT + kk * 8], LDT);
                cvt_tf32_a(fa[mt]);
            }
#pragma unroll
            for (int nt = 0; nt < 4; nt++) {
                FragBc fb;
                wmma::load_matrix_sync(fb, &sB[(wn * 64 + nt * 16) * LDT + kk * 8], LDT);
                cvt_tf32_b(fb);
                wmma::mma_sync(fc[0][nt], fa[0], fb, fc[0][nt]);
                wmma::mma_sync(fc[1][nt], fa[1], fb, fc[1][nt]);
            }
        }
        __syncthreads();
    }
    float* strip = sA + w * 640;
#pragma unroll
    for (int ph = 0; ph < 4; ph++) {
        int mt = ph >> 1, np = ph & 1;
        wmma::store_matrix_sync(strip, fc[mt][np * 2], LDT, wmma::mem_row_major);
        wmma::store_matrix_sync(strip + 16, fc[mt][np * 2 + 1], LDT, wmma::mem_row_major);
        __syncwarp();
#pragma unroll
        for (int rep = 0; rep < 4; rep++) {
            int rl = (lane >> 3) + rep * 4;
            int cl = (lane & 7) * 4;
            float4 acc4 = *(float4*)&strip[rl * LDT + cl];
            int grow = wm * 32 + mt * 16 + rl;   // j
            int gcol = wn * 64 + np * 32 + cl;   // i
            int tsrc = Dd * grow + r - 1;
            float4 u4 = *(const float4*)&u[((size_t)b * Tt + tsrc) * CTRL];
            float4 zv = *(const float4*)&Zb[(size_t)tsrc * LAT + gcol];
            float4 res;
            res.x = acc4.x + zv.x + dot4(bm[gcol + 0], u4);
            res.y = acc4.y + zv.y + dot4(bm[gcol + 1], u4);
            res.z = acc4.z + zv.z + dot4(bm[gcol + 2], u4);
            res.w = acc4.w + zv.w + dot4(bm[gcol + 3], u4);
            *(float4*)&Zb[(size_t)(tsrc + 1) * LAT + gcol] = res;
        }
        __syncwarp();
    }
}

// ---------------- decimated sequential scan: 128 steps with A^8 ----------------
__global__ void __launch_bounds__(128, 3)
k_scan(const float* __restrict__ x_init, const float* __restrict__ Wenc,
       const float* __restrict__ benc) {
    int b = blockIdx.x;
    int i = threadIdx.x;

    __shared__ float zs[2][LAT];
    __shared__ float xi[16];

    ulonglong2 a[32];
    const ulonglong2* Ab = (const ulonglong2*)(g_A8 + (size_t)b * (LAT * LAT) + (size_t)i * LAT);
#pragma unroll
    for (int t = 0; t < 32; t++) a[t] = Ab[t];

    if (i < STATE) xi[i] = x_init[b * STATE + i];
    __syncthreads();

    float z0 = benc[i];
#pragma unroll
    for (int s = 0; s < STATE; s++) z0 += xi[s] * Wenc[s * LAT + i];
    zs[0][i] = z0;
    g_z[((size_t)b * (Tt + 1)) * LAT + i] = z0;
    __syncthreads();

    const float* dbase = g_P + (size_t)b * Jn * LAT;
    float ci = dbase[i];
    int cur = 0;

    for (int k = 0; k < Jn; k++) {
        float cnext = (k + 1 < Jn) ? dbase[(k + 1) * LAT + i] : 0.f;

        const ulonglong2* zv2 = (const ulonglong2*)zs[cur];
        unsigned long long acc0 = pack2(ci, 0.f);
        unsigned long long acc1 = 0ULL;
        unsigned long long acc2 = 0ULL;
        unsigned long long acc3 = 0ULL;
#pragma unroll
        for (int t = 0; t < 32; t += 2) {
            ulonglong2 zva = zv2[t];
            ulonglong2 zvb = zv2[t + 1];
            ffma2(acc0, a[t].x, zva.x);
            ffma2(acc1, a[t].y, zva.y);
            ffma2(acc2, a[t + 1].x, zvb.x);
            ffma2(acc3, a[t + 1].y, zvb.y);
        }
        float s0, s1, s2, s3, s4, s5, s6, s7;
        unpack2(acc0, s0, s1);
        unpack2(acc1, s2, s3);
        unpack2(acc2, s4, s5);
        unpack2(acc3, s6, s7);
        float zn = ((s0 + s2) + (s1 + s3)) + ((s4 + s6) + (s5 + s7));

        zs[cur ^ 1][i] = zn;
        g_z[((size_t)b * (Tt + 1) + Dd * (k + 1)) * LAT + i] = zn;
        ci = cnext;
        __syncthreads();
        cur ^= 1;
    }
}

// ---------------- decode + slice normalization ----------------
__global__ void k_dec(const float* __restrict__ Wdec, const float* __restrict__ bdec,
                      float* __restrict__ out) {
    __shared__ float Wt[STATE * LAT];
    __shared__ float bs[STATE];
    int tid = threadIdx.x;
    for (int idx = tid; idx < STATE * LAT; idx += 256) {
        int o = idx >> 7, c = idx & 127;
        Wt[idx] = Wdec[c * STATE + o];
    }
    if (tid < STATE) bs[tid] = bdec[tid];
    __syncthreads();

    int warp = tid >> 5, lane = tid & 31;
    size_t row = (size_t)blockIdx.x * 8 + warp;
    if (row >= (size_t)Bn * (Tt + 1)) return;

    float4 zv = ((const float4*)g_z)[row * 32 + lane];

    float s[STATE];
#pragma unroll
    for (int o = 0; o < STATE; o++) {
        float4 wv = ((const float4*)Wt)[o * 32 + lane];
        float p = zv.x * wv.x + zv.y * wv.y + zv.z * wv.z + zv.w * wv.w;
        p += __shfl_xor_sync(0xFFFFFFFFu, p, 16);
        p += __shfl_xor_sync(0xFFFFFFFFu, p, 8);
        p += __shfl_xor_sync(0xFFFFFFFFu, p, 4);
        p += __shfl_xor_sync(0xFFFFFFFFu, p, 2);
        p += __shfl_xor_sync(0xFFFFFFFFu, p, 1);
        s[o] = p + bs[o];
    }
    float nrm = sqrtf(s[3] * s[3] + s[4] * s[4] + s[5] * s[5] + s[6] * s[6]);
    float inv = 1.0f / fmaxf(nrm, 1e-12f);
#pragma unroll
    for (int o = 0; o < STATE; o++) {
        float v = s[o];
        if (o >= 3 && o < 7) v *= inv;
        if (lane == o) out[row * STATE + o] = v;
    }
}

// ---------------- launcher ----------------
extern "C" void kernel_launch(void* const* d_in, const int* in_sizes, int n_in,
                              void* d_out, int out_size) {
    const float* x_history = (const float*)d_in[0];
    const float* u_history = (const float*)d_in[1];
    const float* x_init    = (const float*)d_in[2];
    const float* u_future  = (const float*)d_in[4];
    const float* W_ctxt    = (const float*)d_in[6];
    const float* b_ctxt    = (const float*)d_in[7];
    const float* W_A       = (const float*)d_in[8];
    const float* b_A       = (const float*)d_in[9];
    const float* W_B       = (const float*)d_in[10];
    const float* b_B       = (const float*)d_in[11];
    const float* W_enc     = (const float*)d_in[12];
    const float* b_enc     = (const float*)d_in[13];
    const float* W_dec     = (const float*)d_in[14];
    const float* b_dec     = (const float*)d_in[15];
    float* out = (float*)d_out;

    float* dE;  cudaGetSymbolAddress((void**)&dE,  g_E);
    float* dE2; cudaGetSymbolAddress((void**)&dE2, g_E2);
    float* dE4; cudaGetSymbolAddress((void**)&dE4, g_E4);
    float* dA8; cudaGetSymbolAddress((void**)&dA8, g_A8);

    k_ctxt<<<Bn, 256>>>(x_history, u_history, W_ctxt, b_ctxt);
    k_gemmE<<<dim3((LAT * LAT) / BN, Bn / BM), 256>>>(W_A, b_A);
    k_gemmB<<<Bn, 256>>>(W_B, b_B);
    k_cinit<<<Bn, 256>>>(u_future);

    // A powers: E2 = (I+E)^2 - I, E4, then A8 = (I+E4)^2 (identity added)
    k_sq<<<Bn, 256>>>(dE,  dE2, 0);
    k_sq<<<Bn, 256>>>(dE2, dE4, 0);
    k_sq<<<Bn, 256>>>(dE4, dA8, 1);

    // Horner: P -> d_j over 7 rounds
    for (int r = 1; r < Dd; r++) k_hor<<<Bn, 256>>>(u_future, r);

    // sequential decimated scan (128 steps)
    k_scan<<<Bn, 128>>>(x_init, W_enc, b_enc);

    // recover intermediate states
    for (int r = 1; r < Dd; r++) k_rec<<<Bn, 256>>>(u_future, r);

    int rows = Bn * (Tt + 1);
    k_dec<<<(rows + 7) / 8, 256>>>(W_dec, b_dec, out);
}

// round 5
// speedup vs baseline: 1.0088x; 1.0088x over previous
#include <cuda_runtime.h>
#include <mma.h>
#include <cstdint>

using namespace nvcuda;

// Problem constants
#define Bn    512
#define Hh    50
#define Tt    1024
#define STATE 13
#define CTRL  4
#define LAT   128
#define HID   256
#define Dd    8            // decimation factor
#define Jn    (Tt / Dd)    // 128 sequential steps / j-tiles per batch

// ---------------- scratch (no allocations allowed) ----------------
__device__ float g_h[Bn * HID];                        // 0.5 MB
__device__ float g_E[(size_t)Bn * LAT * LAT];          // 32 MB   delta (A = I + delta)
__device__ float g_E2[(size_t)Bn * LAT * LAT];         // 32 MB   E2 = (I+E)^2 - I
__device__ float g_E4[(size_t)Bn * LAT * LAT];         // 32 MB
__device__ float g_A8[(size_t)Bn * LAT * LAT];         // 32 MB   A^8 (identity included)
__device__ float g_P[(size_t)Bn * Jn * LAT];           // 33.5 MB Horner state -> d_j
__device__ float g_Bm[Bn * LAT * CTRL];                // 1 MB
__device__ float g_z[(size_t)Bn * (Tt + 1) * LAT];     // 268.8 MB z trajectory

// ---------------- f32x2 packed FMA helpers ----------------
__device__ __forceinline__ unsigned long long pack2(float x, float y) {
    unsigned long long r;
    asm("mov.b64 %0, {%1, %2};" : "=l"(r) : "f"(x), "f"(y));
    return r;
}
__device__ __forceinline__ void unpack2(unsigned long long v, float& x, float& y) {
    asm("mov.b64 {%0, %1}, %2;" : "=f"(x), "=f"(y) : "l"(v));
}
__device__ __forceinline__ void ffma2(unsigned long long& d, unsigned long long a,
                                      unsigned long long b) {
    asm("fma.rn.f32x2 %0, %1, %2, %3;" : "=l"(d) : "l"(a), "l"(b), "l"(d));
}
__device__ __forceinline__ float dot4(float4 a, float4 b) {
    return a.x * b.x + a.y * b.y + a.z * b.z + a.w * b.w;
}

// ---------------- kernel 1: context mean + tanh MLP ----------------
__global__ void k_ctxt(const float* __restrict__ xh, const float* __restrict__ uh,
                       const float* __restrict__ Wc, const float* __restrict__ bc) {
    int b = blockIdx.x;
    int tid = threadIdx.x;
    __shared__ float m[STATE + CTRL];

    if (tid < STATE + CTRL) {
        float s = 0.f;
        if (tid < STATE) {
            const float* p = xh + (size_t)b * Hh * STATE + tid;
            for (int r = 0; r < Hh; r++) s += p[r * STATE];
        } else {
            const float* p = uh + (size_t)b * Hh * CTRL + (tid - STATE);
            for (int r = 0; r < Hh; r++) s += p[r * CTRL];
        }
        m[tid] = s * (1.0f / (float)Hh);
    }
    __syncthreads();

    float acc = bc[tid];
#pragma unroll
    for (int c = 0; c < STATE + CTRL; c++) acc += m[c] * Wc[c * HID + tid];
    g_h[b * HID + tid] = tanhf(acc);
}

// ---------------- kernel 2: E = h @ W_A + b_A  (FFMA2 tiled GEMM, NO identity) ----
#define BM 32
#define BN 256
#define BK 16
__global__ void __launch_bounds__(256)
k_gemmE(const float* __restrict__ WA, const float* __restrict__ bA) {
    __shared__ float hs[BK][BM + 4];
    __shared__ float Ws[BK][BN];
    int tid = threadIdx.x;
    int c0 = blockIdx.x * BN;
    int b0 = blockIdx.y * BM;
    int ry = tid >> 5;
    int cx = tid & 31;

    unsigned long long acc[4][4];
#pragma unroll
    for (int i = 0; i < 4; i++)
#pragma unroll
        for (int j = 0; j < 4; j++) acc[i][j] = 0ULL;

    for (int k0 = 0; k0 < HID; k0 += BK) {
        for (int idx = tid; idx < BM * BK; idx += 256) {
            int bb = idx >> 4, kk = idx & 15;
            hs[kk][bb] = g_h[(b0 + bb) * HID + k0 + kk];
        }
        for (int idx = tid; idx < (BK * BN) / 4; idx += 256) {
            int kk = idx >> 6, cc4 = idx & 63;
            *(float4*)&Ws[kk][cc4 * 4] =
                *(const float4*)&WA[(size_t)(k0 + kk) * (LAT * LAT) + c0 + cc4 * 4];
        }
        __syncthreads();
#pragma unroll
        for (int kk = 0; kk < BK; kk++) {
            unsigned long long aa[4];
#pragma unroll
            for (int i = 0; i < 4; i++) {
                float av = hs[kk][ry * 4 + i];
                aa[i] = pack2(av, av);
            }
            ulonglong2 w01 = *(const ulonglong2*)&Ws[kk][cx * 8];
            ulonglong2 w23 = *(const ulonglong2*)&Ws[kk][cx * 8 + 4];
#pragma unroll
            for (int i = 0; i < 4; i++) {
                ffma2(acc[i][0], aa[i], w01.x);
                ffma2(acc[i][1], aa[i], w01.y);
                ffma2(acc[i][2], aa[i], w23.x);
                ffma2(acc[i][3], aa[i], w23.y);
            }
        }
        __syncthreads();
    }
#pragma unroll
    for (int i = 0; i < 4; i++) {
        int b = b0 + ry * 4 + i;
        float v[8];
#pragma unroll
        for (int j = 0; j < 4; j++) unpack2(acc[i][j], v[j * 2], v[j * 2 + 1]);
#pragma unroll
        for (int j = 0; j < 8; j++) v[j] += bA[c0 + cx * 8 + j];
        float* dst = g_E + (size_t)b * (LAT * LAT) + c0 + cx * 8;
        *(float4*)dst = make_float4(v[0], v[1], v[2], v[3]);
        *(float4*)(dst + 4) = make_float4(v[4], v[5], v[6], v[7]);
    }
}

// ---------------- kernel 3: B_mat = h @ W_B + b_B ----------------
__global__ void k_gemmB(const float* __restrict__ WB, const float* __restrict__ bB) {
    int b = blockIdx.x;
    int tid = threadIdx.x;
    __shared__ float hs[HID];
    hs[tid] = g_h[b * HID + tid];
    __syncthreads();
    for (int c = tid; c < LAT * CTRL; c += 256) {
        float acc = bB[c];
#pragma unroll 8
        for (int k = 0; k < HID; k++) acc += hs[k] * WB[k * (LAT * CTRL) + c];
        g_Bm[b * (LAT * CTRL) + c] = acc;
    }
}

// ---------------- kernel: P_0[b][j][i] = c_{8j}[i] = Bm[b] @ u[b][8j] -------------
__global__ void k_cinit(const float* __restrict__ u) {
    int b = blockIdx.x;
    int tid = threadIdx.x;
    const float4* bm = (const float4*)g_Bm + b * LAT;
    for (int idx = tid; idx < Jn * LAT; idx += 256) {
        int j = idx >> 7, i = idx & 127;
        float4 u4 = *(const float4*)&u[((size_t)b * Tt + Dd * j) * CTRL];
        g_P[((size_t)b * Jn + j) * LAT + i] = dot4(bm[i], u4);
    }
}

// =====================================================================
// wmma tf32 helpers: each CTA computes one [128,128,128] batch GEMM.
// Warp layout: 8 warps = (wm 0..3: 32 rows) x (wn 0..1: 64 cols).
// Per warp: C frags fc[2 m-tiles][4 n-tiles] of m16n16k8 f32.
// =====================================================================
#define LDT 40   // smem tile leading dim (floats)

typedef wmma::fragment<wmma::matrix_a, 16, 16, 8, wmma::precision::tf32, wmma::row_major> FragA;
typedef wmma::fragment<wmma::matrix_b, 16, 16, 8, wmma::precision::tf32, wmma::col_major> FragBc;
typedef wmma::fragment<wmma::matrix_b, 16, 16, 8, wmma::precision::tf32, wmma::row_major> FragBr;
typedef wmma::fragment<wmma::accumulator, 16, 16, 8, float> FragC;

__device__ __forceinline__ void cvt_tf32_a(FragA& f) {
#pragma unroll
    for (int e = 0; e < f.num_elements; e++) f.x[e] = wmma::__float_to_tf32(f.x[e]);
}
template <typename FB>
__device__ __forceinline__ void cvt_tf32_b(FB& f) {
#pragma unroll
    for (int e = 0; e < f.num_elements; e++) f.x[e] = wmma::__float_to_tf32(f.x[e]);
}

// ---------------- squaring: out = in@in + 2*in (+I on last) ----------------
__global__ void __launch_bounds__(256, 2)
k_sq(const float* __restrict__ in, float* __restrict__ out, int addI) {
    __shared__ float sA[128 * LDT];        // A rows (also epilogue scratch)
    __shared__ float sB[32 * 136];         // B row-major chunk
    int b = blockIdx.x, tid = threadIdx.x, w = tid >> 5, lane = tid & 31;
    int wm = w & 3, wn = w >> 2;
    const float* Inb = in + (size_t)b * LAT * LAT;
    float* Outb = out + (size_t)b * LAT * LAT;

    FragC fc[2][4];
#pragma unroll
    for (int mt = 0; mt < 2; mt++)
#pragma unroll
        for (int nt = 0; nt < 4; nt++) wmma::fill_fragment(fc[mt][nt], 0.f);

    for (int k0 = 0; k0 < 128; k0 += 32) {
        for (int t = tid; t < 1024; t += 256) {
            int row = t >> 3, c4 = (t & 7) * 4;
            *(float4*)&sA[row * LDT + c4] = *(const float4*)&Inb[row * 128 + k0 + c4];
        }
        for (int t = tid; t < 1024; t += 256) {
            int kk = t >> 5, c4 = (t & 31) * 4;
            *(float4*)&sB[kk * 136 + c4] = *(const float4*)&Inb[(k0 + kk) * 128 + c4];
        }
        __syncthreads();
#pragma unroll
        for (int kk = 0; kk < 4; kk++) {
            FragA fa[2];
#pragma unroll
            for (int mt = 0; mt < 2; mt++) {
                wmma::load_matrix_sync(fa[mt], &sA[(wm * 32 + mt * 16) * LDT + kk * 8], LDT);
                cvt_tf32_a(fa[mt]);
            }
#pragma unroll
            for (int nt = 0; nt < 4; nt++) {
                FragBr fb;
                wmma::load_matrix_sync(fb, &sB[(kk * 8) * 136 + wn * 64 + nt * 16], 136);
                cvt_tf32_b(fb);
                wmma::mma_sync(fc[0][nt], fa[0], fb, fc[0][nt]);
                wmma::mma_sync(fc[1][nt], fa[1], fb, fc[1][nt]);
            }
        }
        __syncthreads();
    }
    // epilogue
    float* strip = sA + w * 640;
#pragma unroll
    for (int ph = 0; ph < 4; ph++) {
        int mt = ph >> 1, np = ph & 1;
        wmma::store_matrix_sync(strip, fc[mt][np * 2], LDT, wmma::mem_row_major);
        wmma::store_matrix_sync(strip + 16, fc[mt][np * 2 + 1], LDT, wmma::mem_row_major);
        __syncwarp();
#pragma unroll
        for (int rep = 0; rep < 4; rep++) {
            int rl = (lane >> 3) + rep * 4;
            int cl = (lane & 7) * 4;
            float4 acc4 = *(float4*)&strip[rl * LDT + cl];
            int grow = wm * 32 + mt * 16 + rl;
            int gcol = wn * 64 + np * 32 + cl;
            float4 iv = *(const float4*)&Inb[grow * 128 + gcol];
            float4 res;
            res.x = acc4.x + 2.f * iv.x + ((addI && grow == gcol + 0) ? 1.f : 0.f);
            res.y = acc4.y + 2.f * iv.y + ((addI && grow == gcol + 1) ? 1.f : 0.f);
            res.z = acc4.z + 2.f * iv.z + ((addI && grow == gcol + 2) ? 1.f : 0.f);
            res.w = acc4.w + 2.f * iv.w + ((addI && grow == gcol + 3) ? 1.f : 0.f);
            *(float4*)&Outb[grow * 128 + gcol] = res;
        }
        __syncwarp();
    }
}

// ---------------- Horner round: P <- P + P@E^T + c_{8j+r}  (in-place) ----------
__global__ void __launch_bounds__(256, 2)
k_hor(const float* __restrict__ u, int r) {
    __shared__ float sA[128 * LDT];
    __shared__ float sB[128 * LDT];
    int b = blockIdx.x, tid = threadIdx.x, w = tid >> 5, lane = tid & 31;
    int wm = w & 3, wn = w >> 2;
    float* Pb = g_P + (size_t)b * Jn * LAT;
    const float* Eb = g_E + (size_t)b * LAT * LAT;
    const float4* bm = (const float4*)g_Bm + b * LAT;

    FragC fc[2][4];
#pragma unroll
    for (int mt = 0; mt < 2; mt++)
#pragma unroll
        for (int nt = 0; nt < 4; nt++) wmma::fill_fragment(fc[mt][nt], 0.f);

    for (int k0 = 0; k0 < 128; k0 += 32) {
        for (int t = tid; t < 1024; t += 256) {
            int row = t >> 3, c4 = (t & 7) * 4;
            *(float4*)&sA[row * LDT + c4] = *(const float4*)&Pb[row * 128 + k0 + c4];
            *(float4*)&sB[row * LDT + c4] = *(const float4*)&Eb[row * 128 + k0 + c4];
        }
        __syncthreads();
#pragma unroll
        for (int kk = 0; kk < 4; kk++) {
            FragA fa[2];
#pragma unroll
            for (int mt = 0; mt < 2; mt++) {
                wmma::load_matrix_sync(fa[mt], &sA[(wm * 32 + mt * 16) * LDT + kk * 8], LDT);
                cvt_tf32_a(fa[mt]);
            }
#pragma unroll
            for (int nt = 0; nt < 4; nt++) {
                FragBc fb;   // col-major view of E => B = E^T
                wmma::load_matrix_sync(fb, &sB[(wn * 64 + nt * 16) * LDT + kk * 8], LDT);
                cvt_tf32_b(fb);
                wmma::mma_sync(fc[0][nt], fa[0], fb, fc[0][nt]);
                wmma::mma_sync(fc[1][nt], fa[1], fb, fc[1][nt]);
            }
        }
        __syncthreads();
    }
    float* strip = sA + w * 640;
#pragma unroll
    for (int ph = 0; ph < 4; ph++) {
        int mt = ph >> 1, np = ph & 1;
        wmma::store_matrix_sync(strip, fc[mt][np * 2], LDT, wmma::mem_row_major);
        wmma::store_matrix_sync(strip + 16, fc[mt][np * 2 + 1], LDT, wmma::mem_row_major);
        __syncwarp();
#pragma unroll
        for (int rep = 0; rep < 4; rep++) {
            int rl = (lane >> 3) + rep * 4;
            int cl = (lane & 7) * 4;
            float4 acc4 = *(float4*)&strip[rl * LDT + cl];
            int grow = wm * 32 + mt * 16 + rl;   // j
            int gcol = wn * 64 + np * 32 + cl;   // i
            int t = Dd * grow + r;
            float4 u4 = *(const float4*)&u[((size_t)b * Tt + t) * CTRL];
            float* outp = &Pb[grow * 128 + gcol];
            float4 pv = *(float4*)outp;
            float4 res;
            res.x = acc4.x + pv.x + dot4(bm[gcol + 0], u4);
            res.y = acc4.y + pv.y + dot4(bm[gcol + 1], u4);
            res.z = acc4.z + pv.z + dot4(bm[gcol + 2], u4);
            res.w = acc4.w + pv.w + dot4(bm[gcol + 3], u4);
            *(float4*)outp = res;
        }
        __syncwarp();
    }
}

// ---------------- recovery round: z_{8j+r} = z_{8j+r-1} + z_prev@E^T + c_{8j+r-1} --
__global__ void __launch_bounds__(256, 2)
k_rec(const float* __restrict__ u, int r) {
    __shared__ float sA[128 * LDT];
    __shared__ float sB[128 * LDT];
    int b = blockIdx.x, tid = threadIdx.x, w = tid >> 5, lane = tid & 31;
    int wm = w & 3, wn = w >> 2;
    const float* Eb = g_E + (size_t)b * LAT * LAT;
    const float4* bm = (const float4*)g_Bm + b * LAT;
    float* Zb = g_z + (size_t)b * (Tt + 1) * LAT;

    FragC fc[2][4];
#pragma unroll
    for (int mt = 0; mt < 2; mt++)
#pragma unroll
        for (int nt = 0; nt < 4; nt++) wmma::fill_fragment(fc[mt][nt], 0.f);

    for (int k0 = 0; k0 < 128; k0 += 32) {
        for (int t = tid; t < 1024; t += 256) {
            int row = t >> 3, c4 = (t & 7) * 4;
            *(float4*)&sA[row * LDT + c4] =
                *(const float4*)&Zb[((size_t)(Dd * row + r - 1)) * LAT + k0 + c4];
            *(float4*)&sB[row * LDT + c4] = *(const float4*)&Eb[row * 128 + k0 + c4];
        }
        __syncthreads();
#pragma unroll
        for (int kk = 0; kk < 4; kk++) {
            FragA fa[2];
#pragma unroll
            for (int mt = 0; mt < 2; mt++) {
                wmma::load_matrix_sync(fa[mt], &sA[(wm * 32 + mt * 16) * LDT + kk * 8], LDT);
                cvt_tf32_a(fa[mt]);
            }
#pragma unroll
            for (int nt = 0; nt < 4; nt++) {
                FragBc fb;
                wmma::load_matrix_sync(fb, &sB[(wn * 64 + nt * 16) * LDT + kk * 8], LDT);
                cvt_tf32_b(fb);
                wmma::mma_sync(fc[0][nt], fa[0], fb, fc[0][nt]);
                wmma::mma_sync(fc[1][nt], fa[1], fb, fc[1][nt]);
            }
        }
        __syncthreads();
    }
    float* strip = sA + w * 640;
#pragma unroll
    for (int ph = 0; ph < 4; ph++) {
        int mt = ph >> 1, np = ph & 1;
        wmma::store_matrix_sync(strip, fc[mt][np * 2], LDT, wmma::mem_row_major);
        wmma::store_matrix_sync(strip + 16, fc[mt][np * 2 + 1], LDT, wmma::mem_row_major);
        __syncwarp();
#pragma unroll
        for (int rep = 0; rep < 4; rep++) {
            int rl = (lane >> 3) + rep * 4;
            int cl = (lane & 7) * 4;
            float4 acc4 = *(float4*)&strip[rl * LDT + cl];
            int grow = wm * 32 + mt * 16 + rl;   // j
            int gcol = wn * 64 + np * 32 + cl;   // i
            int tsrc = Dd * grow + r - 1;
            float4 u4 = *(const float4*)&u[((size_t)b * Tt + tsrc) * CTRL];
            float4 zv = *(const float4*)&Zb[(size_t)tsrc * LAT + gcol];
            float4 res;
            res.x = acc4.x + zv.x + dot4(bm[gcol + 0], u4);
            res.y = acc4.y + zv.y + dot4(bm[gcol + 1], u4);
            res.z = acc4.z + zv.z + dot4(bm[gcol + 2], u4);
            res.w = acc4.w + zv.w + dot4(bm[gcol + 3], u4);
            *(float4*)&Zb[(size_t)(tsrc + 1) * LAT + gcol] = res;
        }
        __syncwarp();
    }
}

// ---------------- decimated sequential scan: 128 steps with A^8 ----------------
__global__ void __launch_bounds__(128, 3)
k_scan(const float* __restrict__ x_init, const float* __restrict__ Wenc,
       const float* __restrict__ benc) {
    int b = blockIdx.x;
    int i = threadIdx.x;

    __shared__ float zs[2][LAT];
    __shared__ float xi[16];

    ulonglong2 a[32];
    const ulonglong2* Ab = (const ulonglong2*)(g_A8 + (size_t)b * (LAT * LAT) + (size_t)i * LAT);
#pragma unroll
    for (int t = 0; t < 32; t++) a[t] = Ab[t];

    if (i < STATE) xi[i] = x_init[b * STATE + i];
    __syncthreads();

    float z0 = benc[i];
#pragma unroll
    for (int s = 0; s < STATE; s++) z0 += xi[s] * Wenc[s * LAT + i];
    zs[0][i] = z0;
    g_z[((size_t)b * (Tt + 1)) * LAT + i] = z0;
    __syncthreads();

    const float* dbase = g_P + (size_t)b * Jn * LAT;
    float ci = dbase[i];
    int cur = 0;

    for (int k = 0; k < Jn; k++) {
        float cnext = (k + 1 < Jn) ? dbase[(k + 1) * LAT + i] : 0.f;

        const ulonglong2* zv2 = (const ulonglong2*)zs[cur];
        unsigned long long acc0 = pack2(ci, 0.f);
        unsigned long long acc1 = 0ULL;
        unsigned long long acc2 = 0ULL;
        unsigned long long acc3 = 0ULL;
#pragma unroll
        for (int t = 0; t < 32; t += 2) {
            ulonglong2 zva = zv2[t];
            ulonglong2 zvb = zv2[t + 1];
            ffma2(acc0, a[t].x, zva.x);
            ffma2(acc1, a[t].y, zva.y);
            ffma2(acc2, a[t + 1].x, zvb.x);
            ffma2(acc3, a[t + 1].y, zvb.y);
        }
        float s0, s1, s2, s3, s4, s5, s6, s7;
        unpack2(acc0, s0, s1);
        unpack2(acc1, s2, s3);
        unpack2(acc2, s4, s5);
        unpack2(acc3, s6, s7);
        float zn = ((s0 + s2) + (s1 + s3)) + ((s4 + s6) + (s5 + s7));

        zs[cur ^ 1][i] = zn;
        g_z[((size_t)b * (Tt + 1) + Dd * (k + 1)) * LAT + i] = zn;
        ci = cnext;
        __syncthreads();
        cur ^= 1;
    }
}

// ---------------- decode + slice normalization ----------------
__global__ void k_dec(const float* __restrict__ Wdec, const float* __restrict__ bdec,
                      float* __restrict__ out) {
    __shared__ float Wt[STATE * LAT];
    __shared__ float bs[STATE];
    int tid = threadIdx.x;
    for (int idx = tid; idx < STATE * LAT; idx += 256) {
        int o = idx >> 7, c = idx & 127;
        Wt[idx] = Wdec[c * STATE + o];
    }
    if (tid < STATE) bs[tid] = bdec[tid];
    __syncthreads();

    int warp = tid >> 5, lane = tid & 31;
    size_t row = (size_t)blockIdx.x * 8 + warp;
    if (row >= (size_t)Bn * (Tt + 1)) return;

    float4 zv = ((const float4*)g_z)[row * 32 + lane];

    float s[STATE];
#pragma unroll
    for (int o = 0; o < STATE; o++) {
        float4 wv = ((const float4*)Wt)[o * 32 + lane];
        float p = zv.x * wv.x + zv.y * wv.y + zv.z * wv.z + zv.w * wv.w;
        p += __shfl_xor_sync(0xFFFFFFFFu, p, 16);
        p += __shfl_xor_sync(0xFFFFFFFFu, p, 8);
        p += __shfl_xor_sync(0xFFFFFFFFu, p, 4);
        p += __shfl_xor_sync(0xFFFFFFFFu, p, 2);
        p += __shfl_xor_sync(0xFFFFFFFFu, p, 1);
        s[o] = p + bs[o];
    }
    float nrm = sqrtf(s[3] * s[3] + s[4] * s[4] + s[5] * s[5] + s[6] * s[6]);
    float inv = 1.0f / fmaxf(nrm, 1e-12f);
#pragma unroll
    for (int o = 0; o < STATE; o++) {
        float v = s[o];
        if (o >= 3 && o < 7) v *= inv;
        if (lane == o) out[row * STATE + o] = v;
    }
}

// ---------------- launcher ----------------
extern "C" void kernel_launch(void* const* d_in, const int* in_sizes, int n_in,
                              void* d_out, int out_size) {
    const float* x_history = (const float*)d_in[0];
    const float* u_history = (const float*)d_in[1];
    const float* x_init    = (const float*)d_in[2];
    const float* u_future  = (const float*)d_in[4];
    const float* W_ctxt    = (const float*)d_in[6];
    const float* b_ctxt    = (const float*)d_in[7];
    const float* W_A       = (const float*)d_in[8];
    const float* b_A       = (const float*)d_in[9];
    const float* W_B       = (const float*)d_in[10];
    const float* b_B       = (const float*)d_in[11];
    const float* W_enc     = (const float*)d_in[12];
    const float* b_enc     = (const float*)d_in[13];
    const float* W_dec     = (const float*)d_in[14];
    const float* b_dec     = (const float*)d_in[15];
    float* out = (float*)d_out;

    float* dE;  cudaGetSymbolAddress((void**)&dE,  g_E);
    float* dE2; cudaGetSymbolAddress((void**)&dE2, g_E2);
    float* dE4; cudaGetSymbolAddress((void**)&dE4, g_E4);
    float* dA8; cudaGetSymbolAddress((void**)&dA8, g_A8);

    k_ctxt<<<Bn, 256>>>(x_history, u_history, W_ctxt, b_ctxt);
    k_gemmE<<<dim3((LAT * LAT) / BN, Bn / BM), 256>>>(W_A, b_A);
    k_gemmB<<<Bn, 256>>>(W_B, b_B);
    k_cinit<<<Bn, 256>>>(u_future);

    // A powers: E2 = (I+E)^2 - I, E4, then A8 = (I+E4)^2 (identity added)
    k_sq<<<Bn, 256>>>(dE,  dE2, 0);
    k_sq<<<Bn, 256>>>(dE2, dE4, 0);
    k_sq<<<Bn, 256>>>(dE4, dA8, 1);

    // Horner: P -> d_j over 7 rounds
    for (int r = 1; r < Dd; r++) k_hor<<<Bn, 256>>>(u_future, r);

    // sequential decimated scan (128 steps)
    k_scan<<<Bn, 128>>>(x_init, W_enc, b_enc);

    // recover intermediate states
    for (int r = 1; r < Dd; r++) k_rec<<<Bn, 256>>>(u_future, r);

    int rows = Bn * (Tt + 1);
    k_dec<<<(rows + 7) / 8, 256>>>(W_dec, b_dec, out);
}